// round 2
// baseline (speedup 1.0000x reference)
#include <cuda_runtime.h>

#define T_STEPS 512
#define BATCH   256
#define INDIM   8
#define HID     512
#define OUTD    5
#define NCTA    96
#define NL0     32
#define THREADS 256
#define WST     516            // padded SMEM row stride (floats): conflict-free B loads
#define NPHASE  (T_STEPS + 1)  // 513 phases (pipelined: phase p -> h0[p], h1[p-1])

// Persistent state (device globals: no allocations allowed)
__device__ float    g_h0[2][BATCH * HID];
__device__ float    g_h1[2][BATCH * HID];
__device__ unsigned g_bar[NPHASE];

__device__ __forceinline__ float to_tf32(float x) {
    float r; asm("cvt.rna.tf32.f32 %0, %1;" : "=f"(r) : "f"(x)); return r;
}
__device__ __forceinline__ float sigmoidf_(float x) {
    return 1.f / (1.f + __expf(-x));
}
__device__ __forceinline__ float tanhf_(float x) {
    float e = __expf(2.f * x);          // overflow -> inf -> returns 1.0 correctly
    return 1.f - 2.f / (e + 1.f);
}
__device__ __forceinline__ void mma_tf32(float* c, const unsigned* a, unsigned b0, unsigned b1) {
    asm volatile(
        "mma.sync.aligned.m16n8k8.row.col.f32.tf32.tf32.f32 "
        "{%0,%1,%2,%3}, {%4,%5,%6,%7}, {%8,%9}, {%0,%1,%2,%3};\n"
        : "+f"(c[0]), "+f"(c[1]), "+f"(c[2]), "+f"(c[3])
        : "r"(a[0]), "r"(a[1]), "r"(a[2]), "r"(a[3]), "r"(b0), "r"(b1));
}
__device__ __forceinline__ float ldcg(const float* p) { return __ldcg(p); }

// Device-wide sense-free barrier: one counter per phase, reset each launch.
__device__ __forceinline__ void grid_barrier(int p) {
    __syncthreads();
    if (threadIdx.x == 0) {
        unsigned* c = &g_bar[p];
        asm volatile("red.release.gpu.global.add.u32 [%0], %1;" :: "l"(c), "r"(1u) : "memory");
        unsigned v;
        do {
            asm volatile("ld.acquire.gpu.global.u32 %0, [%1];" : "=r"(v) : "l"(c) : "memory");
        } while (v < NCTA);
    }
    __syncthreads();
}

__global__ void reset_kernel() {
    int tid = blockIdx.x * blockDim.x + threadIdx.x;
    int stride = gridDim.x * blockDim.x;
    for (int i = tid; i < BATCH * HID; i += stride) { g_h0[1][i] = 0.f; g_h1[1][i] = 0.f; }
    if (tid < NPHASE) g_bar[tid] = 0u;
}

extern __shared__ float smem[];

__global__ void __launch_bounds__(THREADS, 1) gru_persistent(
    const float* __restrict__ x,
    const float* __restrict__ Wih0, const float* __restrict__ Whh0,
    const float* __restrict__ bih0, const float* __restrict__ bhh0,
    const float* __restrict__ Wih1, const float* __restrict__ Whh1,
    const float* __restrict__ bih1, const float* __restrict__ bhh1,
    const float* __restrict__ Wout, const float* __restrict__ bout,
    float* __restrict__ out)
{
    float* Wsm   = smem;                  // 48 x WST  (tf32 weight tile)
    float* xsm   = Wsm + 48 * WST;        // 256 x 8   (x_t tile, layer0 only)
    float* wihsm = xsm + BATCH * INDIM;   // 48 x 8    (W_ih0 slice, fp32)
    float* bihsm = wihsm + 48 * INDIM;    // 48
    float* bhhsm = bihsm + 48;            // 48

    const int tid  = threadIdx.x;
    const int cta  = blockIdx.x;
    const bool l0  = (cta < NL0);
    const int lane = tid & 31;
    const int warp = tid >> 5;
    const int gid  = lane >> 2;
    const int q    = lane & 3;
    const int rowbase = warp * 32;

    // ---- stage weights ONCE (persistent kernel) ----
    if (l0) {
        const int U0 = cta * 16;
        for (int i = tid; i < 48 * HID; i += THREADS) {
            int j = i >> 9, k = i & (HID - 1);
            int g = (j < 16) ? (U0 + j) : (j < 32) ? (512 + U0 + j - 16) : (1024 + U0 + j - 32);
            Wsm[j * WST + k] = to_tf32(Whh0[g * HID + k]);
        }
        for (int i = tid; i < 48 * INDIM; i += THREADS) {
            int j = i >> 3, k = i & 7;
            int g = (j < 16) ? (U0 + j) : (j < 32) ? (512 + U0 + j - 16) : (1024 + U0 + j - 32);
            wihsm[j * INDIM + k] = Wih0[g * INDIM + k];
        }
        if (tid < 48) {
            int j = tid;
            int g = (j < 16) ? (U0 + j) : (j < 32) ? (512 + U0 + j - 16) : (1024 + U0 + j - 32);
            bihsm[j] = bih0[g];
            bhhsm[j] = bhh0[g];
        }
    } else {
        const int U1 = (cta - NL0) * 8;
        for (int i = tid; i < 48 * HID; i += THREADS) {
            int j = i >> 9, k = i & (HID - 1);
            int jj = (j < 24) ? j : (j - 24);
            int g = (jj < 8) ? (U1 + jj) : (jj < 16) ? (512 + U1 + jj - 8) : (1024 + U1 + jj - 16);
            const float* W = (j < 24) ? Wih1 : Whh1;
            Wsm[j * WST + k] = to_tf32(W[g * HID + k]);
        }
        if (tid < 24) {
            int jj = tid;
            int g = (jj < 8) ? (U1 + jj) : (jj < 16) ? (512 + U1 + jj - 8) : (1024 + U1 + jj - 16);
            bihsm[jj] = bih1[g];
            bhhsm[jj] = bhh1[g];
        }
    }
    __syncthreads();

    for (int p = 0; p < NPHASE; ++p) {
        if (l0) {
            if (p < T_STEPS) {
                // stage x_t (2048 floats)
                const float4* xp = (const float4*)(x + (size_t)p * BATCH * INDIM);
                float4* xd = (float4*)xsm;
                xd[tid] = xp[tid];
                xd[tid + THREADS] = xp[tid + THREADS];
                __syncthreads();

                const float* A  = g_h0[(unsigned)(p - 1) & 1u];  // h0[p-1]
                float* Hn = g_h0[p & 1];                          // h0[p]
                const int U0 = cta * 16;

                float acc[2][6][4];
                #pragma unroll
                for (int mt = 0; mt < 2; ++mt)
                    #pragma unroll
                    for (int nt = 0; nt < 6; ++nt)
                        #pragma unroll
                        for (int e = 0; e < 4; ++e) acc[mt][nt][e] = 0.f;

                #pragma unroll 4
                for (int kc = 0; kc < HID / 8; ++kc) {
                    const int k = kc * 8 + q;
                    unsigned a[2][4];
                    #pragma unroll
                    for (int mt = 0; mt < 2; ++mt) {
                        const int rb = (rowbase + mt * 16 + gid) * HID;
                        a[mt][0] = __float_as_uint(ldcg(A + rb + k));
                        a[mt][1] = __float_as_uint(ldcg(A + rb + 8 * HID + k));
                        a[mt][2] = __float_as_uint(ldcg(A + rb + k + 4));
                        a[mt][3] = __float_as_uint(ldcg(A + rb + 8 * HID + k + 4));
                    }
                    #pragma unroll
                    for (int nt = 0; nt < 6; ++nt) {
                        unsigned b0 = __float_as_uint(Wsm[(nt * 8 + gid) * WST + k]);
                        unsigned b1 = __float_as_uint(Wsm[(nt * 8 + gid) * WST + k + 4]);
                        mma_tf32(acc[0][nt], a[0], b0, b1);
                        mma_tf32(acc[1][nt], a[1], b0, b1);
                    }
                }

                // epilogue: GRU cell, thread-local (cols 0..15 r | 16..31 z | 32..47 n)
                #pragma unroll
                for (int mt = 0; mt < 2; ++mt)
                #pragma unroll
                for (int hh = 0; hh < 2; ++hh) {
                    const int row = rowbase + mt * 16 + gid + hh * 8;
                    const float* xrow = xsm + row * INDIM;
                    #pragma unroll
                    for (int g2 = 0; g2 < 2; ++g2)
                    #pragma unroll
                    for (int e = 0; e < 2; ++e) {
                        const int u = g2 * 8 + q * 2 + e;
                        const int cr = hh * 2 + e;
                        float hr = acc[mt][0 + g2][cr];
                        float hz = acc[mt][2 + g2][cr];
                        float hn = acc[mt][4 + g2][cr];
                        float xr = bihsm[u], xz = bihsm[16 + u], xn = bihsm[32 + u];
                        #pragma unroll
                        for (int k = 0; k < INDIM; ++k) {
                            float xv = xrow[k];
                            xr += xv * wihsm[u * INDIM + k];
                            xz += xv * wihsm[(16 + u) * INDIM + k];
                            xn += xv * wihsm[(32 + u) * INDIM + k];
                        }
                        float rg = sigmoidf_(xr + hr + bhhsm[u]);
                        float zg = sigmoidf_(xz + hz + bhhsm[16 + u]);
                        float ng = tanhf_(xn + rg * (hn + bhhsm[32 + u]));
                        float hp = ldcg(A + row * HID + U0 + u);
                        __stcg(Hn + row * HID + U0 + u, to_tf32((1.f - zg) * ng + zg * hp));
                    }
                }
            }
        } else {
            if (p >= 1) {
                const float* A0 = g_h0[(unsigned)(p - 1) & 1u];  // h0[p-1]
                const float* A1 = g_h1[(unsigned)p & 1u];        // h1[p-2]
                float* Hn = g_h1[(unsigned)(p - 1) & 1u];        // h1[p-1]
                const int U1 = (cta - NL0) * 8;

                float acc[2][6][4];
                #pragma unroll
                for (int mt = 0; mt < 2; ++mt)
                    #pragma unroll
                    for (int nt = 0; nt < 6; ++nt)
                        #pragma unroll
                        for (int e = 0; e < 4; ++e) acc[mt][nt][e] = 0.f;

                #pragma unroll 4
                for (int kc = 0; kc < HID / 8; ++kc) {
                    const int k = kc * 8 + q;
                    unsigned a0[2][4], a1[2][4];
                    #pragma unroll
                    for (int mt = 0; mt < 2; ++mt) {
                        const int rb = (rowbase + mt * 16 + gid) * HID;
                        a0[mt][0] = __float_as_uint(ldcg(A0 + rb + k));
                        a0[mt][1] = __float_as_uint(ldcg(A0 + rb + 8 * HID + k));
                        a0[mt][2] = __float_as_uint(ldcg(A0 + rb + k + 4));
                        a0[mt][3] = __float_as_uint(ldcg(A0 + rb + 8 * HID + k + 4));
                        a1[mt][0] = __float_as_uint(ldcg(A1 + rb + k));
                        a1[mt][1] = __float_as_uint(ldcg(A1 + rb + 8 * HID + k));
                        a1[mt][2] = __float_as_uint(ldcg(A1 + rb + k + 4));
                        a1[mt][3] = __float_as_uint(ldcg(A1 + rb + 8 * HID + k + 4));
                    }
                    #pragma unroll
                    for (int nt = 0; nt < 6; ++nt) {
                        unsigned b0 = __float_as_uint(Wsm[(nt * 8 + gid) * WST + k]);
                        unsigned b1 = __float_as_uint(Wsm[(nt * 8 + gid) * WST + k + 4]);
                        if (nt < 3) {
                            mma_tf32(acc[0][nt], a0[0], b0, b1);
                            mma_tf32(acc[1][nt], a0[1], b0, b1);
                        } else {
                            mma_tf32(acc[0][nt], a1[0], b0, b1);
                            mma_tf32(acc[1][nt], a1[1], b0, b1);
                        }
                    }
                }

                // epilogue: cols 0..7 gi_r | 8..15 gi_z | 16..23 gi_n | 24..31 gh_r | 32..39 gh_z | 40..47 gh_n
                #pragma unroll
                for (int mt = 0; mt < 2; ++mt)
                #pragma unroll
                for (int hh = 0; hh < 2; ++hh) {
                    const int row = rowbase + mt * 16 + gid + hh * 8;
                    #pragma unroll
                    for (int e = 0; e < 2; ++e) {
                        const int u = q * 2 + e;
                        const int cr = hh * 2 + e;
                        float ir  = acc[mt][0][cr];
                        float iz  = acc[mt][1][cr];
                        float inn = acc[mt][2][cr];
                        float hr  = acc[mt][3][cr];
                        float hz  = acc[mt][4][cr];
                        float hn  = acc[mt][5][cr];
                        float rg = sigmoidf_(ir + bihsm[u] + hr + bhhsm[u]);
                        float zg = sigmoidf_(iz + bihsm[8 + u] + hz + bhhsm[8 + u]);
                        float ng = tanhf_(inn + bihsm[16 + u] + rg * (hn + bhhsm[16 + u]));
                        float hp = ldcg(A1 + row * HID + U1 + u);
                        __stcg(Hn + row * HID + U1 + u, to_tf32((1.f - zg) * ng + zg * hp));
                    }
                }
            }
        }
        grid_barrier(p);
    }

    // linear head: out = h1[T-1] @ Wout^T + bout   (CTA 0, one row per thread)
    if (cta == 0) {
        const float* hrow = g_h1[(T_STEPS - 1) & 1] + (size_t)tid * HID;
        float acc[OUTD];
        #pragma unroll
        for (int o = 0; o < OUTD; ++o) acc[o] = bout[o];
        #pragma unroll 4
        for (int k = 0; k < HID; ++k) {
            float hv = ldcg(hrow + k);
            #pragma unroll
            for (int o = 0; o < OUTD; ++o) acc[o] += hv * __ldg(&Wout[o * HID + k]);
        }
        #pragma unroll
        for (int o = 0; o < OUTD; ++o) out[tid * OUTD + o] = acc[o];
    }
}

extern "C" void kernel_launch(void* const* d_in, const int* in_sizes, int n_in,
                              void* d_out, int out_size) {
    const float* x     = (const float*)d_in[0];
    const float* Wih0  = (const float*)d_in[1];
    const float* Whh0  = (const float*)d_in[2];
    const float* bih0  = (const float*)d_in[3];
    const float* bhh0  = (const float*)d_in[4];
    const float* Wih1  = (const float*)d_in[5];
    const float* Whh1  = (const float*)d_in[6];
    const float* bih1  = (const float*)d_in[7];
    const float* bhh1  = (const float*)d_in[8];
    const float* Wout  = (const float*)d_in[9];
    const float* bout  = (const float*)d_in[10];
    float* out = (float*)d_out;

    const int smem_bytes = (48 * WST + BATCH * INDIM + 48 * INDIM + 96) * sizeof(float);
    cudaFuncSetAttribute(gru_persistent, cudaFuncAttributeMaxDynamicSharedMemorySize, smem_bytes);

    reset_kernel<<<128, 256>>>();
    gru_persistent<<<NCTA, THREADS, smem_bytes>>>(
        x, Wih0, Whh0, bih0, bhh0, Wih1, Whh1, bih1, bhh1, Wout, bout, out);
}

// round 3
// speedup vs baseline: 1.8540x; 1.8540x over previous
#include <cuda_runtime.h>

#define T_STEPS 512
#define BATCH   256
#define INDIM   8
#define HID     512
#define OUTD    5
#define NCTA    128
#define NL0     64
#define THREADS 256
#define WST     520
#define XCH     52
#define NPHASE  (T_STEPS + 1)

__device__ float    g_h0[2][BATCH * HID];
__device__ float    g_h1[2][BATCH * HID];
__device__ unsigned g_bar[NPHASE];

// element (k,row) lives at ((k&3)*32 + (k>>4))*1024 + row*4 + ((k>>2)&3)
__device__ __forceinline__ int hoff(int k, int row) {
    return (((k & 3) * 32 + (k >> 4)) << 10) + (row << 2) + ((k >> 2) & 3);
}
// within each 8-k chunk, put (k, k+4) adjacent: chunk base + q*2, q*2+1
__device__ __forceinline__ int wperm(int k) {
    return (k & ~7) + ((k & 3) << 1) + ((k >> 2) & 1);
}
__device__ __forceinline__ float to_tf32(float x) {
    float r; asm("cvt.rna.tf32.f32 %0, %1;" : "=f"(r) : "f"(x)); return r;
}
__device__ __forceinline__ float sig_(float x) { return 1.f / (1.f + __expf(-x)); }
__device__ __forceinline__ float tanh_(float x) {
    float e = __expf(2.f * x); return 1.f - 2.f / (e + 1.f);
}
__device__ __forceinline__ void mma_tf32(float* c, const unsigned* a, float2 b) {
    asm volatile(
        "mma.sync.aligned.m16n8k8.row.col.f32.tf32.tf32.f32 "
        "{%0,%1,%2,%3}, {%4,%5,%6,%7}, {%8,%9}, {%0,%1,%2,%3};\n"
        : "+f"(c[0]), "+f"(c[1]), "+f"(c[2]), "+f"(c[3])
        : "r"(a[0]), "r"(a[1]), "r"(a[2]), "r"(a[3]),
          "r"(__float_as_uint(b.x)), "r"(__float_as_uint(b.y)));
}

__device__ __forceinline__ void grid_barrier(int p) {
    __syncthreads();
    if (threadIdx.x == 0) {
        unsigned* c = &g_bar[p];
        asm volatile("red.release.gpu.global.add.u32 [%0], %1;" :: "l"(c), "r"(1u) : "memory");
        unsigned v;
        do {
            asm volatile("ld.acquire.gpu.global.u32 %0, [%1];" : "=r"(v) : "l"(c) : "memory");
        } while (v < NCTA);
    }
    __syncthreads();
}

__global__ void reset_kernel() {
    int tid = blockIdx.x * blockDim.x + threadIdx.x;
    int stride = gridDim.x * blockDim.x;
    for (int i = tid; i < BATCH * HID; i += stride) { g_h0[1][i] = 0.f; g_h1[1][i] = 0.f; }
    if (tid < NPHASE) g_bar[tid] = 0u;
}

extern __shared__ float smem[];

__global__ void __launch_bounds__(THREADS, 1) gru_persistent(
    const float* __restrict__ x,
    const float* __restrict__ Wih0, const float* __restrict__ Whh0,
    const float* __restrict__ bih0, const float* __restrict__ bhh0,
    const float* __restrict__ Wih1, const float* __restrict__ Whh1,
    const float* __restrict__ bih1, const float* __restrict__ bhh1,
    const float* __restrict__ Wout, const float* __restrict__ bout,
    float* __restrict__ out)
{
    const int tid  = threadIdx.x;
    const int cta  = blockIdx.x;
    const bool l0  = (cta < NL0);
    const int lane = tid & 31;
    const int warp = tid >> 5;
    const int gid  = lane >> 2;
    const int q    = lane & 3;
    const int hi   = warp >> 2;          // l1: 0 = gi side, 1 = gh side
    const int mw   = warp & 3;

    float* Wsm = smem;
    float* aux = smem + (l0 ? 48 : 96) * WST;
    const int ms = (l0 ? cta : cta - NL0) & 1;
    const int U  = ((l0 ? cta : cta - NL0) >> 1) * 16;   // first unit of this slice

    // ---------------- stage weights once ----------------
    if (l0) {
        for (int i = tid; i < 48 * HID; i += THREADS) {
            int j = i >> 9, k = i & (HID - 1);
            int g = j >> 4, uu = j & 15;
            Wsm[j * WST + wperm(k)] = to_tf32(Whh0[(g * HID + U + uu) * HID + k]);
        }
        float* wih = aux + 1024; float* bi = aux + 1408; float* bh = aux + 1456;
        for (int i = tid; i < 48 * INDIM; i += THREADS) {
            int j = i >> 3, kk = i & 7;
            wih[i] = Wih0[((j >> 4) * HID + U + (j & 15)) * INDIM + kk];
        }
        if (tid < 48) {
            int g = tid >> 4, uu = tid & 15;
            bi[tid] = bih0[g * HID + U + uu]; bh[tid] = bhh0[g * HID + U + uu];
        }
    } else {
        for (int i = tid; i < 96 * HID; i += THREADS) {
            int j = i >> 9, k = i & (HID - 1);
            int loc = (j < 48) ? j : j - 48;
            int g = loc >> 4, uu = loc & 15;
            const float* W = (j < 48) ? Wih1 : Whh1;
            Wsm[j * WST + wperm(k)] = to_tf32(W[(g * HID + U + uu) * HID + k]);
        }
        float* bi = aux + 128 * XCH; float* bh = bi + 48;
        if (tid < 48) {
            int g = tid >> 4, uu = tid & 15;
            bi[tid] = bih1[g * HID + U + uu]; bh[tid] = bhh1[g * HID + U + uu];
        }
    }
    __syncthreads();

    // ---------------- phase loop ----------------
    for (int p = 0; p < NPHASE; ++p) {
        if (l0) {
            if (p < T_STEPS) {
                const float4* xp = (const float4*)(x + ((size_t)p * BATCH + ms * 128) * INDIM);
                ((float4*)aux)[tid] = xp[tid];          // 128 rows x 8 = 256 float4
                __syncthreads();

                const float* A = g_h0[(p + 1) & 1];     // h0[p-1]
                float* Hn = g_h0[p & 1];                // h0[p]
                const int r0 = ms * 128 + warp * 16 + gid;

                float acc[6][4];
                #pragma unroll
                for (int n = 0; n < 6; ++n)
                    #pragma unroll
                    for (int e = 0; e < 4; ++e) acc[n][e] = 0.f;

                #pragma unroll 2
                for (int t = 0; t < 32; ++t) {
                    float4 v0 = __ldcg((const float4*)(A + ((q * 32 + t) << 10) + (r0 << 2)));
                    float4 v1 = __ldcg((const float4*)(A + ((q * 32 + t) << 10) + ((r0 + 8) << 2)));
                    #pragma unroll
                    for (int c = 0; c < 2; ++c) {
                        const int kb = (t * 2 + c) * 8 + q * 2;
                        unsigned a[4];
                        a[0] = __float_as_uint(c ? v0.z : v0.x);
                        a[1] = __float_as_uint(c ? v1.z : v1.x);
                        a[2] = __float_as_uint(c ? v0.w : v0.y);
                        a[3] = __float_as_uint(c ? v1.w : v1.y);
                        #pragma unroll
                        for (int n = 0; n < 6; ++n)
                            mma_tf32(acc[n], a, *(const float2*)&Wsm[(n * 8 + gid) * WST + kb]);
                    }
                }

                const float* wih = aux + 1024; const float* bi = aux + 1408; const float* bh = aux + 1456;
                #pragma unroll
                for (int hh = 0; hh < 2; ++hh)
                #pragma unroll
                for (int sub = 0; sub < 2; ++sub)
                #pragma unroll
                for (int e = 0; e < 2; ++e) {
                    const int rl = warp * 16 + hh * 8 + gid;
                    const int rg2 = ms * 128 + rl;
                    const int uu = sub * 8 + q * 2 + e;
                    const int cr = hh * 2 + e;
                    float hr = acc[sub][cr], hz = acc[2 + sub][cr], hn = acc[4 + sub][cr];
                    float xr = bi[uu], xz = bi[16 + uu], xn = bi[32 + uu];
                    const float* xrow = aux + rl * INDIM;
                    #pragma unroll
                    for (int k = 0; k < INDIM; ++k) {
                        float xv = xrow[k];
                        xr += xv * wih[uu * INDIM + k];
                        xz += xv * wih[(16 + uu) * INDIM + k];
                        xn += xv * wih[(32 + uu) * INDIM + k];
                    }
                    float r = sig_(xr + hr + bh[uu]);
                    float z = sig_(xz + hz + bh[16 + uu]);
                    float n = tanh_(xn + r * (hn + bh[32 + uu]));
                    float hp = __ldcg(A + hoff(U + uu, rg2));
                    __stcg(Hn + hoff(U + uu, rg2), to_tf32((1.f - z) * n + z * hp));
                }
            }
        } else if (p >= 1) {
            const float* A0 = g_h0[(p + 1) & 1];   // h0[p-1]
            const float* A1 = g_h1[p & 1];         // h1[p-2]
            float* Hn = g_h1[(p + 1) & 1];         // h1[p-1]
            const float* A = hi ? A1 : A0;
            const int rbase = ms * 128 + mw * 32;

            float acc[2][6][4];
            #pragma unroll
            for (int m = 0; m < 2; ++m)
                #pragma unroll
                for (int n = 0; n < 6; ++n)
                    #pragma unroll
                    for (int e = 0; e < 4; ++e) acc[m][n][e] = 0.f;

            #pragma unroll 2
            for (int t = 0; t < 32; ++t) {
                float4 v[2][2];
                #pragma unroll
                for (int m = 0; m < 2; ++m)
                    #pragma unroll
                    for (int rg2 = 0; rg2 < 2; ++rg2)
                        v[m][rg2] = __ldcg((const float4*)(A + ((q * 32 + t) << 10)
                                        + ((rbase + m * 16 + rg2 * 8 + gid) << 2)));
                #pragma unroll
                for (int c = 0; c < 2; ++c) {
                    const int kb = (t * 2 + c) * 8 + q * 2;
                    unsigned a[2][4];
                    #pragma unroll
                    for (int m = 0; m < 2; ++m) {
                        a[m][0] = __float_as_uint(c ? v[m][0].z : v[m][0].x);
                        a[m][1] = __float_as_uint(c ? v[m][1].z : v[m][1].x);
                        a[m][2] = __float_as_uint(c ? v[m][0].w : v[m][0].y);
                        a[m][3] = __float_as_uint(c ? v[m][1].w : v[m][1].y);
                    }
                    #pragma unroll
                    for (int n = 0; n < 6; ++n) {
                        float2 b = *(const float2*)&Wsm[(hi * 48 + n * 8 + gid) * WST + kb];
                        mma_tf32(acc[0][n], a[0], b);
                        mma_tf32(acc[1][n], a[1], b);
                    }
                }
            }

            float* xch = aux;
            if (hi) {      // gh side publishes raw gate pre-activations
                #pragma unroll
                for (int m = 0; m < 2; ++m)
                #pragma unroll
                for (int n = 0; n < 6; ++n)
                #pragma unroll
                for (int hh = 0; hh < 2; ++hh)
                #pragma unroll
                for (int e = 0; e < 2; ++e) {
                    int rl = mw * 32 + m * 16 + hh * 8 + gid;
                    xch[rl * XCH + n * 8 + q * 2 + e] = acc[m][n][hh * 2 + e];
                }
            }
            __syncthreads();
            if (!hi) {     // gi side combines + cell math + store
                const float* bi = aux + 128 * XCH; const float* bh = bi + 48;
                #pragma unroll
                for (int m = 0; m < 2; ++m)
                #pragma unroll
                for (int hh = 0; hh < 2; ++hh)
                #pragma unroll
                for (int sub = 0; sub < 2; ++sub)
                #pragma unroll
                for (int e = 0; e < 2; ++e) {
                    const int rl = mw * 32 + m * 16 + hh * 8 + gid;
                    const int rg2 = ms * 128 + rl;
                    const int uu = sub * 8 + q * 2 + e;
                    const int cr = hh * 2 + e;
                    const int xo = rl * XCH + sub * 8 + q * 2 + e;
                    float ir = acc[m][sub][cr], iz = acc[m][2 + sub][cr], in_ = acc[m][4 + sub][cr];
                    float hr = xch[xo], hz = xch[xo + 16], hn = xch[xo + 32];
                    float r = sig_(ir + bi[uu] + hr + bh[uu]);
                    float z = sig_(iz + bi[16 + uu] + hz + bh[16 + uu]);
                    float n = tanh_(in_ + bi[32 + uu] + r * (hn + bh[32 + uu]));
                    float hp = __ldcg(A1 + hoff(U + uu, rg2));
                    __stcg(Hn + hoff(U + uu, rg2), to_tf32((1.f - z) * n + z * hp));
                }
            }
        }
        grid_barrier(p);
    }

    // linear head: h1[T-1] lives in g_h1[1] (written at p=512)
    if (cta == 0) {
        const float* hb = g_h1[1];
        float acc[OUTD];
        #pragma unroll
        for (int o = 0; o < OUTD; ++o) acc[o] = bout[o];
        for (int k = 0; k < HID; ++k) {
            float hv = __ldcg(hb + hoff(k, tid));
            #pragma unroll
            for (int o = 0; o < OUTD; ++o) acc[o] += hv * __ldg(&Wout[o * HID + k]);
        }
        #pragma unroll
        for (int o = 0; o < OUTD; ++o) out[tid * OUTD + o] = acc[o];
    }
}

extern "C" void kernel_launch(void* const* d_in, const int* in_sizes, int n_in,
                              void* d_out, int out_size) {
    const float* x    = (const float*)d_in[0];
    const float* Wih0 = (const float*)d_in[1];
    const float* Whh0 = (const float*)d_in[2];
    const float* bih0 = (const float*)d_in[3];
    const float* bhh0 = (const float*)d_in[4];
    const float* Wih1 = (const float*)d_in[5];
    const float* Whh1 = (const float*)d_in[6];
    const float* bih1 = (const float*)d_in[7];
    const float* bhh1 = (const float*)d_in[8];
    const float* Wout = (const float*)d_in[9];
    const float* bout = (const float*)d_in[10];
    float* out = (float*)d_out;

    // l1 CTA is the big one: 96*520 + 128*52 + 96 words = 226,688 bytes
    const int smem_bytes = (96 * WST + 128 * XCH + 96) * sizeof(float);
    static int configured = 0;
    if (!configured) {
        cudaFuncSetAttribute(gru_persistent, cudaFuncAttributeMaxDynamicSharedMemorySize, smem_bytes);
        configured = 1;
    }

    reset_kernel<<<128, 256>>>();
    gru_persistent<<<NCTA, THREADS, smem_bytes>>>(
        x, Wih0, Whh0, bih0, bhh0, Wih1, Whh1, bih1, bhh1, Wout, bout, out);
}

// round 5
// speedup vs baseline: 2.2961x; 1.2384x over previous
#include <cuda_runtime.h>

#define T_STEPS 512
#define BATCH   256
#define INDIM   8
#define HID     512
#define OUTD    5
#define NCTA    128
#define THREADS 512
#define WST     528            // words; WST/4 % 8 == 4 -> conflict-free LDS.128 on B
#define XCHS    74             // K-reduction exchange stride (even: float2 aligned)
#define NPHASE  (T_STEPS + 1)

__device__ float    g_h0[2][BATCH * HID];
__device__ float    g_h1[2][BATCH * HID];
__device__ unsigned g_bar[NPHASE];

// hidden element (k,row) at ((k&3)*32 + (k>>4))*1024 + row*4 + ((k>>2)&3)
// -> float4 at (q,t,row) = { k=16t+q, +4, +8, +12 } : both c-chunks' frag pairs
__device__ __forceinline__ int hoff(int k, int row) {
    return (((k & 3) * 32 + (k >> 4)) << 10) + (row << 2) + ((k >> 2) & 3);
}
// weight in-16-block permutation: pos = (k&3)*4 + ((k>>2)&3) -> {c0lo,c0hi,c1lo,c1hi} per q
__device__ __forceinline__ int wp16(int k) {
    return (k & ~15) + ((k & 3) << 2) + ((k >> 2) & 3);
}
__device__ __forceinline__ float to_tf32(float x) {
    float r; asm("cvt.rna.tf32.f32 %0, %1;" : "=f"(r) : "f"(x)); return r;
}
__device__ __forceinline__ float sig_(float x) { return 1.f / (1.f + __expf(-x)); }
__device__ __forceinline__ float tanh_(float x) {
    float e = __expf(2.f * x); return 1.f - 2.f / (e + 1.f);
}
__device__ __forceinline__ void mma_tf32(float* c, const unsigned* a, float bx, float by) {
    asm volatile(
        "mma.sync.aligned.m16n8k8.row.col.f32.tf32.tf32.f32 "
        "{%0,%1,%2,%3}, {%4,%5,%6,%7}, {%8,%9}, {%0,%1,%2,%3};\n"
        : "+f"(c[0]), "+f"(c[1]), "+f"(c[2]), "+f"(c[3])
        : "r"(a[0]), "r"(a[1]), "r"(a[2]), "r"(a[3]),
          "r"(__float_as_uint(bx)), "r"(__float_as_uint(by)));
}

__device__ __forceinline__ void grid_barrier(int p) {
    __syncthreads();
    if (threadIdx.x == 0) {
        unsigned* c = &g_bar[p];
        asm volatile("red.release.gpu.global.add.u32 [%0], %1;" :: "l"(c), "r"(1u) : "memory");
        unsigned v;
        do {
            asm volatile("ld.acquire.gpu.global.u32 %0, [%1];" : "=r"(v) : "l"(c) : "memory");
        } while (v < NCTA);
    }
    __syncthreads();
}

__global__ void reset_kernel() {
    int tid = blockIdx.x * blockDim.x + threadIdx.x;
    int stride = gridDim.x * blockDim.x;
    for (int i = tid; i < BATCH * HID; i += stride) { g_h0[1][i] = 0.f; g_h1[1][i] = 0.f; }
    if (tid < NPHASE) g_bar[tid] = 0u;
}

extern __shared__ float smem[];

// Uniform CTA: cta i -> ms = i&1 (row half), us = i>>1 (8 hidden units U=us*8).
// Per phase each CTA computes, for its 8 units x 128 rows:
//   side0: layer0 hh-GEMM (A = h0[p-1])  -> h0[p]   (with x-path epilogue)
//   side1: layer1 gi-GEMM (A = h0[p-1])  \
//   side2: layer1 gh-GEMM (A = h1[p-2])  / -> h1[p-1] (thread-local cell)
// Warps: mg = warp&7 (16 rows), ks = warp>>3 (K half); K-reduction via SMEM.
__global__ void __launch_bounds__(THREADS, 1) gru_persistent(
    const float* __restrict__ x,
    const float* __restrict__ Wih0, const float* __restrict__ Whh0,
    const float* __restrict__ bih0, const float* __restrict__ bhh0,
    const float* __restrict__ Wih1, const float* __restrict__ Whh1,
    const float* __restrict__ bih1, const float* __restrict__ bhh1,
    const float* __restrict__ Wout, const float* __restrict__ bout,
    float* __restrict__ out)
{
    float* Wsm = smem;                       // 72 rows x WST (tiles j=0..8, row j*8+u)
    float* xsm = smem + 72 * WST;            // 128 x 8
    float* wih = xsm + 1024;                 // 24 x 8
    float* b0i = wih + 192;  float* b0h = b0i + 24;
    float* b1i = b0h + 24;   float* b1h = b1i + 24;
    float* xch = b1h + 24;                   // 128 x XCHS

    const int tid  = threadIdx.x;
    const int cta  = blockIdx.x;
    const int lane = tid & 31;
    const int warp = tid >> 5;
    const int gid  = lane >> 2;
    const int q    = lane & 3;
    const int mg   = warp & 7;
    const int ks   = warp >> 3;
    const int ms   = cta & 1;
    const int U    = (cta >> 1) * 8;

    // ---- stage weights once: rows j=side*24 + g3*8 + u ----
    for (int i = tid; i < 72 * HID; i += THREADS) {
        int j = i >> 9, k = i & (HID - 1);
        int side = j / 24, jj = j % 24;
        int g3 = jj >> 3, u = jj & 7;
        const float* W = (side == 0) ? Whh0 : (side == 1) ? Wih1 : Whh1;
        Wsm[j * WST + wp16(k)] = to_tf32(W[(g3 * HID + U + u) * HID + k]);
    }
    for (int i = tid; i < 24 * INDIM; i += THREADS) {
        int j = i >> 3, kk = i & 7;
        wih[i] = Wih0[((j >> 3) * HID + U + (j & 7)) * INDIM + kk];
    }
    if (tid < 24) {
        int g3 = tid >> 3, u = tid & 7;
        b0i[tid] = bih0[g3 * HID + U + u]; b0h[tid] = bhh0[g3 * HID + U + u];
        b1i[tid] = bih1[g3 * HID + U + u]; b1h[tid] = bhh1[g3 * HID + U + u];
    }
    __syncthreads();

    for (int p = 0; p < NPHASE; ++p) {
        const float* A0 = g_h0[(p + 1) & 1];     // h0[p-1]
        const float* A1 = g_h1[p & 1];           // h1[p-2]
        float* H0n = g_h0[p & 1];                // h0[p]
        float* H1n = g_h1[(p + 1) & 1];          // h1[p-1]

        // stage x_t slice (guard OOB at p==T_STEPS; result unread then)
        if (tid < 256) {
            int pp = (p < T_STEPS) ? p : (T_STEPS - 1);
            ((float4*)xsm)[tid] =
                ((const float4*)(x + ((size_t)pp * BATCH + ms * 128) * INDIM))[tid];
        }

        const int r0 = ms * 128 + mg * 16 + gid;

        // prefetch previous-h values for the z-blend (ks==0 warps do epilogue)
        float hp0[2][2], hp1[2][2];
        if (ks == 0) {
            #pragma unroll
            for (int hh = 0; hh < 2; ++hh)
                #pragma unroll
                for (int e = 0; e < 2; ++e) {
                    int uu = q * 2 + e;
                    int rg = ms * 128 + mg * 16 + hh * 8 + gid;
                    hp0[hh][e] = __ldcg(A0 + hoff(U + uu, rg));
                    hp1[hh][e] = __ldcg(A1 + hoff(U + uu, rg));
                }
        }

        float acc[9][4];
        #pragma unroll
        for (int j = 0; j < 9; ++j)
            #pragma unroll
            for (int e = 0; e < 4; ++e) acc[j][e] = 0.f;

        #pragma unroll 2
        for (int tt = 0; tt < 16; ++tt) {
            const int t = ks * 16 + tt;
            const int boff = t * 16 + q * 4;
            const float* a0b = A0 + ((q * 32 + t) << 10);
            const float* a1b = A1 + ((q * 32 + t) << 10);
            float4 v0 = __ldcg((const float4*)(a0b + (r0 << 2)));
            float4 v1 = __ldcg((const float4*)(a0b + ((r0 + 8) << 2)));
            float4 w0 = __ldcg((const float4*)(a1b + (r0 << 2)));
            float4 w1 = __ldcg((const float4*)(a1b + ((r0 + 8) << 2)));
            unsigned p0[4] = {__float_as_uint(v0.x), __float_as_uint(v1.x),
                              __float_as_uint(v0.y), __float_as_uint(v1.y)};
            unsigned p1[4] = {__float_as_uint(v0.z), __float_as_uint(v1.z),
                              __float_as_uint(v0.w), __float_as_uint(v1.w)};
            unsigned q0[4] = {__float_as_uint(w0.x), __float_as_uint(w1.x),
                              __float_as_uint(w0.y), __float_as_uint(w1.y)};
            unsigned q1[4] = {__float_as_uint(w0.z), __float_as_uint(w1.z),
                              __float_as_uint(w0.w), __float_as_uint(w1.w)};
            #pragma unroll
            for (int j = 0; j < 6; ++j) {            // sides 0,1 : A = h0[p-1]
                float4 b = *(const float4*)&Wsm[(j * 8 + gid) * WST + boff];
                mma_tf32(acc[j], p0, b.x, b.y);
                mma_tf32(acc[j], p1, b.z, b.w);
            }
            #pragma unroll
            for (int j = 6; j < 9; ++j) {            // side 2 : A = h1[p-2]
                float4 b = *(const float4*)&Wsm[(j * 8 + gid) * WST + boff];
                mma_tf32(acc[j], q0, b.x, b.y);
                mma_tf32(acc[j], q1, b.z, b.w);
            }
        }

        // K-split reduction: ks=1 publishes, ks=0 combines
        if (ks == 1) {
            #pragma unroll
            for (int j = 0; j < 9; ++j)
                #pragma unroll
                for (int hh = 0; hh < 2; ++hh) {
                    int rl = mg * 16 + hh * 8 + gid;
                    *(float2*)&xch[rl * XCHS + j * 8 + q * 2] =
                        make_float2(acc[j][hh * 2], acc[j][hh * 2 + 1]);
                }
        }
        __syncthreads();
        if (ks == 0) {
            #pragma unroll
            for (int j = 0; j < 9; ++j)
                #pragma unroll
                for (int hh = 0; hh < 2; ++hh) {
                    int rl = mg * 16 + hh * 8 + gid;
                    float2 pp = *(const float2*)&xch[rl * XCHS + j * 8 + q * 2];
                    acc[j][hh * 2] += pp.x; acc[j][hh * 2 + 1] += pp.y;
                }

            #pragma unroll
            for (int hh = 0; hh < 2; ++hh)
            #pragma unroll
            for (int e = 0; e < 2; ++e) {
                const int uu = q * 2 + e;
                const int cr = hh * 2 + e;
                const int rl = mg * 16 + hh * 8 + gid;
                const int rg = ms * 128 + rl;
                // layer0 cell (x-path scalar, K=8)
                float xr = b0i[uu], xz = b0i[8 + uu], xn = b0i[16 + uu];
                const float* xrow = xsm + rl * INDIM;
                #pragma unroll
                for (int k = 0; k < INDIM; ++k) {
                    float xv = xrow[k];
                    xr += xv * wih[uu * INDIM + k];
                    xz += xv * wih[(8 + uu) * INDIM + k];
                    xn += xv * wih[(16 + uu) * INDIM + k];
                }
                float r = sig_(xr + acc[0][cr] + b0h[uu]);
                float z = sig_(xz + acc[1][cr] + b0h[8 + uu]);
                float n = tanh_(xn + r * (acc[2][cr] + b0h[16 + uu]));
                __stcg(H0n + hoff(U + uu, rg), to_tf32((1.f - z) * n + z * hp0[hh][e]));
                // layer1 cell (gi in acc[3..5], gh in acc[6..8] -- same thread)
                if (p >= 1) {
                    float r1 = sig_(acc[3][cr] + b1i[uu] + acc[6][cr] + b1h[uu]);
                    float z1 = sig_(acc[4][cr] + b1i[8 + uu] + acc[7][cr] + b1h[8 + uu]);
                    float n1 = tanh_(acc[5][cr] + b1i[16 + uu]
                                     + r1 * (acc[8][cr] + b1h[16 + uu]));
                    __stcg(H1n + hoff(U + uu, rg), to_tf32((1.f - z1) * n1 + z1 * hp1[hh][e]));
                }
            }
        }
        grid_barrier(p);
    }

    // linear head: h1[T-1] is in g_h1[1] (written at phase p=512)
    if (cta == 0 && tid < 256) {
        const float* hb = g_h1[1];
        float acc[OUTD];
        #pragma unroll
        for (int o = 0; o < OUTD; ++o) acc[o] = bout[o];
        for (int k = 0; k < HID; ++k) {
            float hv = __ldcg(hb + hoff(k, tid));
            #pragma unroll
            for (int o = 0; o < OUTD; ++o) acc[o] += hv * __ldg(&Wout[o * HID + k]);
        }
        #pragma unroll
        for (int o = 0; o < OUTD; ++o) out[tid * OUTD + o] = acc[o];
    }
}

extern "C" void kernel_launch(void* const* d_in, const int* in_sizes, int n_in,
                              void* d_out, int out_size) {
    const float* x    = (const float*)d_in[0];
    const float* Wih0 = (const float*)d_in[1];
    const float* Whh0 = (const float*)d_in[2];
    const float* bih0 = (const float*)d_in[3];
    const float* bhh0 = (const float*)d_in[4];
    const float* Wih1 = (const float*)d_in[5];
    const float* Whh1 = (const float*)d_in[6];
    const float* bih1 = (const float*)d_in[7];
    const float* bhh1 = (const float*)d_in[8];
    const float* Wout = (const float*)d_in[9];
    const float* bout = (const float*)d_in[10];
    float* out = (float*)d_out;

    // 72*528 + 1024 + 192 + 96 + 128*74 = 48,784 words = 195,136 B
    const int smem_bytes = (72 * WST + 1024 + 192 + 96 + 128 * XCHS) * sizeof(float);
    static int configured = 0;
    if (!configured) {
        cudaFuncSetAttribute(gru_persistent, cudaFuncAttributeMaxDynamicSharedMemorySize,
                             smem_bytes);
        configured = 1;
    }

    reset_kernel<<<128, 256>>>();
    gru_persistent<<<NCTA, THREADS, smem_bytes>>>(
        x, Wih0, Whh0, bih0, bhh0, Wih1, Whh1, bih1, bhh1, Wout, bout, out);
}

// round 7
// speedup vs baseline: 2.5849x; 1.1258x over previous
#include <cuda_runtime.h>

#define T_STEPS 512
#define BATCH   256
#define INDIM   8
#define HID     512
#define OUTD    5
#define NCTA    128
#define THREADS 384
#define WST     528            // words; chunk idx (4*gid+q)%8 distinct per 8-lane phase
#define XST     52             // exchange row stride (words)
#define NPHASE  (T_STEPS + 1)

__device__ float    g_h0[2][BATCH * HID];
__device__ float    g_h1[2][BATCH * HID];
__device__ unsigned g_bar[NPHASE];

// hidden element (k,row) at ((k&3)*32 + (k>>4))*1024 + row*4 + ((k>>2)&3)
__device__ __forceinline__ int hoff(int k, int row) {
    return (((k & 3) * 32 + (k >> 4)) << 10) + (row << 2) + ((k >> 2) & 3);
}
// weight in-16-block permutation: pos = (k&3)*4 + ((k>>2)&3)
__device__ __forceinline__ int wp16(int k) {
    return (k & ~15) + ((k & 3) << 2) + ((k >> 2) & 3);
}
__device__ __forceinline__ float to_tf32(float x) {
    float r; asm("cvt.rna.tf32.f32 %0, %1;" : "=f"(r) : "f"(x)); return r;
}
__device__ __forceinline__ float sig_(float x) { return 1.f / (1.f + __expf(-x)); }
__device__ __forceinline__ float tanh_(float x) {
    float e = __expf(2.f * x); return 1.f - 2.f / (e + 1.f);
}
__device__ __forceinline__ void mma_tf32(float* c, const unsigned* a, float bx, float by) {
    asm volatile(
        "mma.sync.aligned.m16n8k8.row.col.f32.tf32.tf32.f32 "
        "{%0,%1,%2,%3}, {%4,%5,%6,%7}, {%8,%9}, {%0,%1,%2,%3};\n"
        : "+f"(c[0]), "+f"(c[1]), "+f"(c[2]), "+f"(c[3])
        : "r"(a[0]), "r"(a[1]), "r"(a[2]), "r"(a[3]),
          "r"(__float_as_uint(bx)), "r"(__float_as_uint(by)));
}

__device__ __forceinline__ void grid_barrier(int p) {
    __syncthreads();
    if (threadIdx.x == 0) {
        unsigned* c = &g_bar[p];
        asm volatile("red.release.gpu.global.add.u32 [%0], %1;" :: "l"(c), "r"(1u) : "memory");
        unsigned v;
        do {
            asm volatile("ld.acquire.gpu.global.u32 %0, [%1];" : "=r"(v) : "l"(c) : "memory");
        } while (v < NCTA);
    }
    __syncthreads();
}

__global__ void reset_kernel() {
    int tid = blockIdx.x * blockDim.x + threadIdx.x;
    int stride = gridDim.x * blockDim.x;
    for (int i = tid; i < BATCH * HID; i += stride) { g_h0[1][i] = 0.f; g_h1[1][i] = 0.f; }
    if (tid < NPHASE) g_bar[tid] = 0u;
}

extern __shared__ float smem[];

// 128 CTAs: ms = cta&1 (128-row half), U = (cta>>1)*8 (8 hidden units).
// 12 warps:
//   grp0 (warps 0-7) = mg(4: 32 rows) x ks(2: K half): sides 0+1 (tiles 0..5, A=h0[p-1])
//   grp1 (warps 8-11) = mg(4): side 2 (tiles 6..8, A=h1[p-2]), full K
// 2 m16-tiles per warp -> each B LDS.128 feeds 4 MMAs.
// Single CONVERGENT __syncthreads between publish and epilogues.
__global__ void __launch_bounds__(THREADS, 1) gru_persistent(
    const float* __restrict__ x,
    const float* __restrict__ Wih0, const float* __restrict__ Whh0,
    const float* __restrict__ bih0, const float* __restrict__ bhh0,
    const float* __restrict__ Wih1, const float* __restrict__ Whh1,
    const float* __restrict__ bih1, const float* __restrict__ bhh1,
    const float* __restrict__ Wout, const float* __restrict__ bout,
    float* __restrict__ out)
{
    float* Wsm = smem;                       // 72 x WST
    float* xsm = smem + 72 * WST;            // 128 x 8
    float* wih = xsm + 1024;                 // 24 x 8
    float* b0i = wih + 192;  float* b0h = b0i + 24;
    float* b1i = b0h + 24;   float* b1h = b1i + 24;
    float* xch0 = b1h + 24;                  // 128 x XST (from ks1: tiles 0..5)
    float* xch1 = xch0 + 128 * XST;          // 128 x XST (from ks0: tiles 3..5)

    const int tid  = threadIdx.x;
    const int cta  = blockIdx.x;
    const int lane = tid & 31;
    const int warp = tid >> 5;
    const int gid  = lane >> 2;
    const int q    = lane & 3;
    const bool g1  = (warp >= 8);
    const int mg   = g1 ? (warp - 8) : (warp & 3);
    const int ks   = g1 ? 0 : (warp >> 2);
    const int ms   = cta & 1;
    const int U    = (cta >> 1) * 8;

    // ---- stage weights once ----
    for (int i = tid; i < 72 * HID; i += THREADS) {
        int j = i >> 9, k = i & (HID - 1);
        int side = j / 24, jj = j % 24;
        int g3 = jj >> 3, u = jj & 7;
        const float* W = (side == 0) ? Whh0 : (side == 1) ? Wih1 : Whh1;
        Wsm[j * WST + wp16(k)] = to_tf32(W[(g3 * HID + U + u) * HID + k]);
    }
    for (int i = tid; i < 24 * INDIM; i += THREADS) {
        int j = i >> 3, kk = i & 7;
        wih[i] = Wih0[((j >> 3) * HID + U + (j & 7)) * INDIM + kk];
    }
    if (tid < 24) {
        int g3 = tid >> 3, u = tid & 7;
        b0i[tid] = bih0[g3 * HID + U + u]; b0h[tid] = bhh0[g3 * HID + U + u];
        b1i[tid] = bih1[g3 * HID + U + u]; b1h[tid] = bhh1[g3 * HID + U + u];
    }
    __syncthreads();

    for (int p = 0; p < NPHASE; ++p) {
        const float* A0 = g_h0[(p + 1) & 1];     // h0[p-1]
        const float* A1 = g_h1[p & 1];           // h1[p-2]
        float* H0n = g_h0[p & 1];                // h0[p]
        float* H1n = g_h1[(p + 1) & 1];          // h1[p-1]

        if (tid < 256) {
            int pp = (p < T_STEPS) ? p : (T_STEPS - 1);
            ((float4*)xsm)[tid] =
                ((const float4*)(x + ((size_t)pp * BATCH + ms * 128) * INDIM))[tid];
        }

        const int r0 = ms * 128 + mg * 32 + gid;
        const float* Ab = g1 ? A1 : A0;

        // prefetch h-prev for the z-blend (epilogue warps only)
        float hp[2][2][2];
        if (g1 || ks == 0) {
            #pragma unroll
            for (int mt = 0; mt < 2; ++mt)
                #pragma unroll
                for (int hh = 0; hh < 2; ++hh)
                    #pragma unroll
                    for (int e = 0; e < 2; ++e) {
                        int rg = ms * 128 + mg * 32 + mt * 16 + hh * 8 + gid;
                        hp[mt][hh][e] = __ldcg(Ab + hoff(U + q * 2 + e, rg));
                    }
        }

        // unified accumulators: grp0 uses [0..5], grp1 uses [0..2]
        float acc[6][2][4];
        #pragma unroll
        for (int j = 0; j < 6; ++j)
            #pragma unroll
            for (int mt = 0; mt < 2; ++mt)
                #pragma unroll
                for (int e = 0; e < 4; ++e) acc[j][mt][e] = 0.f;

        if (!g1) {
            // ---------- grp0: sides 0+1 (A = h0[p-1]), K half ----------
            #pragma unroll 2
            for (int tt = 0; tt < 16; ++tt) {
                const int t = ks * 16 + tt;
                const float* ab = Ab + ((q * 32 + t) << 10);
                float4 v00 = __ldcg((const float4*)(ab + (r0 << 2)));
                float4 v01 = __ldcg((const float4*)(ab + ((r0 + 8) << 2)));
                float4 v10 = __ldcg((const float4*)(ab + ((r0 + 16) << 2)));
                float4 v11 = __ldcg((const float4*)(ab + ((r0 + 24) << 2)));
                unsigned p0[2][4] = {
                    {__float_as_uint(v00.x), __float_as_uint(v01.x),
                     __float_as_uint(v00.y), __float_as_uint(v01.y)},
                    {__float_as_uint(v10.x), __float_as_uint(v11.x),
                     __float_as_uint(v10.y), __float_as_uint(v11.y)}};
                unsigned p1[2][4] = {
                    {__float_as_uint(v00.z), __float_as_uint(v01.z),
                     __float_as_uint(v00.w), __float_as_uint(v01.w)},
                    {__float_as_uint(v10.z), __float_as_uint(v11.z),
                     __float_as_uint(v10.w), __float_as_uint(v11.w)}};
                const int boff = t * 16 + q * 4;
                #pragma unroll
                for (int j = 0; j < 6; ++j) {
                    float4 b = *(const float4*)&Wsm[(j * 8 + gid) * WST + boff];
                    mma_tf32(acc[j][0], p0[0], b.x, b.y);
                    mma_tf32(acc[j][0], p1[0], b.z, b.w);
                    mma_tf32(acc[j][1], p0[1], b.x, b.y);
                    mma_tf32(acc[j][1], p1[1], b.z, b.w);
                }
            }
            // publish partials (stores only; sync comes at convergent point)
            if (ks == 1) {
                #pragma unroll
                for (int j = 0; j < 6; ++j)
                    #pragma unroll
                    for (int mt = 0; mt < 2; ++mt)
                        #pragma unroll
                        for (int hh = 0; hh < 2; ++hh) {
                            int rl = mg * 32 + mt * 16 + hh * 8 + gid;
                            *(float2*)&xch0[rl * XST + j * 8 + q * 2] =
                                make_float2(acc[j][mt][hh * 2], acc[j][mt][hh * 2 + 1]);
                        }
            } else {
                #pragma unroll
                for (int j = 3; j < 6; ++j)
                    #pragma unroll
                    for (int mt = 0; mt < 2; ++mt)
                        #pragma unroll
                        for (int hh = 0; hh < 2; ++hh) {
                            int rl = mg * 32 + mt * 16 + hh * 8 + gid;
                            *(float2*)&xch1[rl * XST + (j - 3) * 8 + q * 2] =
                                make_float2(acc[j][mt][hh * 2], acc[j][mt][hh * 2 + 1]);
                        }
            }
        } else {
            // ---------- grp1: side 2 (A = h1[p-2]), full K ----------
            #pragma unroll 2
            for (int t = 0; t < 32; ++t) {
                const float* ab = Ab + ((q * 32 + t) << 10);
                float4 v00 = __ldcg((const float4*)(ab + (r0 << 2)));
                float4 v01 = __ldcg((const float4*)(ab + ((r0 + 8) << 2)));
                float4 v10 = __ldcg((const float4*)(ab + ((r0 + 16) << 2)));
                float4 v11 = __ldcg((const float4*)(ab + ((r0 + 24) << 2)));
                unsigned p0[2][4] = {
                    {__float_as_uint(v00.x), __float_as_uint(v01.x),
                     __float_as_uint(v00.y), __float_as_uint(v01.y)},
                    {__float_as_uint(v10.x), __float_as_uint(v11.x),
                     __float_as_uint(v10.y), __float_as_uint(v11.y)}};
                unsigned p1[2][4] = {
                    {__float_as_uint(v00.z), __float_as_uint(v01.z),
                     __float_as_uint(v00.w), __float_as_uint(v01.w)},
                    {__float_as_uint(v10.z), __float_as_uint(v11.z),
                     __float_as_uint(v10.w), __float_as_uint(v11.w)}};
                const int boff = t * 16 + q * 4;
                #pragma unroll
                for (int j = 0; j < 3; ++j) {
                    float4 b = *(const float4*)&Wsm[((j + 6) * 8 + gid) * WST + boff];
                    mma_tf32(acc[j][0], p0[0], b.x, b.y);
                    mma_tf32(acc[j][0], p1[0], b.z, b.w);
                    mma_tf32(acc[j][1], p0[1], b.x, b.y);
                    mma_tf32(acc[j][1], p1[1], b.z, b.w);
                }
            }
        }

        __syncthreads();   // single convergent rendezvous: partials visible

        if (!g1 && ks == 0) {
            // ---------- layer0 cells ----------
            #pragma unroll
            for (int mt = 0; mt < 2; ++mt)
            #pragma unroll
            for (int hh = 0; hh < 2; ++hh) {
                const int rl = mg * 32 + mt * 16 + hh * 8 + gid;
                const int rg = ms * 128 + rl;
                const float* xrow = xsm + rl * INDIM;
                float2 pr = *(const float2*)&xch0[rl * XST + 0 * 8 + q * 2];
                float2 pz = *(const float2*)&xch0[rl * XST + 1 * 8 + q * 2];
                float2 pn = *(const float2*)&xch0[rl * XST + 2 * 8 + q * 2];
                #pragma unroll
                for (int e = 0; e < 2; ++e) {
                    const int uu = q * 2 + e;
                    const int cr = hh * 2 + e;
                    float hr = acc[0][mt][cr] + (e ? pr.y : pr.x);
                    float hz = acc[1][mt][cr] + (e ? pz.y : pz.x);
                    float hn = acc[2][mt][cr] + (e ? pn.y : pn.x);
                    float xr = b0i[uu], xz = b0i[8 + uu], xn = b0i[16 + uu];
                    #pragma unroll
                    for (int k = 0; k < INDIM; ++k) {
                        float xv = xrow[k];
                        xr += xv * wih[uu * INDIM + k];
                        xz += xv * wih[(8 + uu) * INDIM + k];
                        xn += xv * wih[(16 + uu) * INDIM + k];
                    }
                    float r = sig_(xr + hr + b0h[uu]);
                    float z = sig_(xz + hz + b0h[8 + uu]);
                    float n = tanh_(xn + r * (hn + b0h[16 + uu]));
                    __stcg(H0n + hoff(U + uu, rg),
                           to_tf32((1.f - z) * n + z * hp[mt][hh][e]));
                }
            }
        } else if (g1 && p >= 1) {
            // ---------- layer1 cells: gi = xch0[3..5] + xch1[0..2]; gh = acc ----------
            #pragma unroll
            for (int mt = 0; mt < 2; ++mt)
            #pragma unroll
            for (int hh = 0; hh < 2; ++hh) {
                const int rl = mg * 32 + mt * 16 + hh * 8 + gid;
                const int rg = ms * 128 + rl;
                float2 ar = *(const float2*)&xch0[rl * XST + 3 * 8 + q * 2];
                float2 az = *(const float2*)&xch0[rl * XST + 4 * 8 + q * 2];
                float2 an = *(const float2*)&xch0[rl * XST + 5 * 8 + q * 2];
                float2 br = *(const float2*)&xch1[rl * XST + 0 * 8 + q * 2];
                float2 bz = *(const float2*)&xch1[rl * XST + 1 * 8 + q * 2];
                float2 bn = *(const float2*)&xch1[rl * XST + 2 * 8 + q * 2];
                #pragma unroll
                for (int e = 0; e < 2; ++e) {
                    const int uu = q * 2 + e;
                    const int cr = hh * 2 + e;
                    float ir  = (e ? ar.y : ar.x) + (e ? br.y : br.x);
                    float iz  = (e ? az.y : az.x) + (e ? bz.y : bz.x);
                    float in_ = (e ? an.y : an.x) + (e ? bn.y : bn.x);
                    float r = sig_(ir + b1i[uu] + acc[0][mt][cr] + b1h[uu]);
                    float z = sig_(iz + b1i[8 + uu] + acc[1][mt][cr] + b1h[8 + uu]);
                    float n = tanh_(in_ + b1i[16 + uu]
                                    + r * (acc[2][mt][cr] + b1h[16 + uu]));
                    __stcg(H1n + hoff(U + uu, rg),
                           to_tf32((1.f - z) * n + z * hp[mt][hh][e]));
                }
            }
        }
        grid_barrier(p);
    }

    // linear head: h1[T-1] in g_h1[1] (written at p=512)
    if (cta == 0 && tid < 256) {
        const float* hb = g_h1[1];
        float acc2[OUTD];
        #pragma unroll
        for (int o = 0; o < OUTD; ++o) acc2[o] = bout[o];
        for (int k = 0; k < HID; ++k) {
            float hv = __ldcg(hb + hoff(k, tid));
            #pragma unroll
            for (int o = 0; o < OUTD; ++o) acc2[o] += hv * __ldg(&Wout[o * HID + k]);
        }
        #pragma unroll
        for (int o = 0; o < OUTD; ++o) out[tid * OUTD + o] = acc2[o];
    }
}

extern "C" void kernel_launch(void* const* d_in, const int* in_sizes, int n_in,
                              void* d_out, int out_size) {
    const float* x    = (const float*)d_in[0];
    const float* Wih0 = (const float*)d_in[1];
    const float* Whh0 = (const float*)d_in[2];
    const float* bih0 = (const float*)d_in[3];
    const float* bhh0 = (const float*)d_in[4];
    const float* Wih1 = (const float*)d_in[5];
    const float* Whh1 = (const float*)d_in[6];
    const float* bih1 = (const float*)d_in[7];
    const float* bhh1 = (const float*)d_in[8];
    const float* Wout = (const float*)d_in[9];
    const float* bout = (const float*)d_in[10];
    float* out = (float*)d_out;

    // 72*528 + 1024 + 192 + 96 + 2*128*52 = 52,640 words = 210,560 B
    const int smem_bytes = (72 * WST + 1024 + 192 + 96 + 2 * 128 * XST) * sizeof(float);
    static int configured = 0;
    if (!configured) {
        cudaFuncSetAttribute(gru_persistent, cudaFuncAttributeMaxDynamicSharedMemorySize,
                             smem_bytes);
        configured = 1;
    }

    reset_kernel<<<128, 256>>>();
    gru_persistent<<<NCTA, THREADS, smem_bytes>>>(
        x, Wih0, Whh0, bih0, bhh0, Wih1, Whh1, bih1, bhh1, Wout, bout, out);
}